// round 11
// baseline (speedup 1.0000x reference)
#include <cuda_runtime.h>
#include <cstdint>

#define B_TOT 16384
#define T_SEQ 784
#define HID   30
#define NCLS  10
#define NJP   16          // 15 h-pairs (cols 0..29) + 1 x-pair
#define RPT   8           // rows per thread (30 padded to 32, 4 subs x 8)
#define SUBS  4
#define WSTRIDE (NJP * RPT + 2)   // 130 u64 per sub: +16B pad => subs hit disjoint banks

typedef unsigned long long u64;

// ---- packed f32x2 helpers (Blackwell FFMA2 path, PTX-only) ----
__device__ __forceinline__ u64 pk2(float lo, float hi) {
    u64 r; asm("mov.b64 %0, {%1, %2};" : "=l"(r) : "f"(lo), "f"(hi)); return r;
}
__device__ __forceinline__ void upk2(float& lo, float& hi, u64 v) {
    asm("mov.b64 {%0, %1}, %2;" : "=f"(lo), "=f"(hi) : "l"(v));
}
__device__ __forceinline__ u64 ffma2(u64 a, u64 b, u64 c) {
    u64 d; asm("fma.rn.f32x2 %0, %1, %2, %3;" : "=l"(d) : "l"(a), "l"(b), "l"(c));
    return d;
}
__device__ __forceinline__ u64 fmul2(u64 a, u64 b) {
    u64 d; asm("mul.rn.f32x2 %0, %1, %2;" : "=l"(d) : "l"(a), "l"(b));
    return d;
}

// 4 threads cooperate on one batch element (sub = tid&3 owns rows 8*sub..8*sub+7,
// rows 30,31 are zero-padded). Each step: every thread contracts the full packed
// h vector (held in registers, identical across the 4 subs) against its 8 weight
// rows from SMEM, applies modReLU to its 8 outputs, then the 15 packed h'-pairs
// are broadcast across the quad with shfl.idx. 2048 warps total -> 3-4 per SMSP.
__global__ void __launch_bounds__(128, 4)
rnn_modrelu_kernel(const float* __restrict__ inputs,   // [B, 784]
                   const float* __restrict__ W_ih,     // [30, 1]
                   const float* __restrict__ W_hh,     // [30, 30]
                   const float* __restrict__ b_mod,    // [30]
                   const float* __restrict__ W_lin,    // [10, 30]
                   const float* __restrict__ b_lin,    // [10]
                   float* __restrict__ out)            // [B, 10]
{
    // wts[sub*WSTRIDE + jp*8 + k] = packed weights for row i=8*sub+k, col pair jp:
    //   jp<15 : (W_hh[i][2jp], W_hh[i][2jp+1])   (zero if i>=30)
    //   jp=15 : (W_ih[i], 0)
    __shared__ __align__(16) u64 wts[SUBS * WSTRIDE];

    const int tid = threadIdx.x;
    for (int idx = tid; idx < SUBS * NJP * RPT; idx += 128) {
        const int s  = idx / (NJP * RPT);
        const int rm = idx % (NJP * RPT);
        const int jp = rm / RPT;
        const int k  = rm % RPT;
        const int i  = s * RPT + k;
        float lo = 0.0f, hi = 0.0f;
        if (i < HID) {
            if (jp < 15) { lo = W_hh[i * HID + 2 * jp]; hi = W_hh[i * HID + 2 * jp + 1]; }
            else         { lo = W_ih[i]; }
        }
        wts[s * WSTRIDE + jp * RPT + k] = pk2(lo, hi);
    }
    __syncthreads();

    const int lane = tid & 31;
    const int sub  = tid & 3;
    const int elem = blockIdx.x * 32 + (tid >> 2);

    float bmr[RPT];
#pragma unroll
    for (int r = 0; r < RPT; r++) {
        const int i = sub * RPT + r;
        bmr[r] = (i < HID) ? __ldg(&b_mod[i]) : 0.0f;
    }

    const float2* __restrict__ xrow =
        reinterpret_cast<const float2*>(inputs + (size_t)elem * T_SEQ);
    const ulonglong2* __restrict__ wp =
        reinterpret_cast<const ulonglong2*>(wts + sub * WSTRIDE);

    u64 hfull[NJP];
#pragma unroll
    for (int p = 0; p < NJP; p++) hfull[p] = 0ull;
    u64 own[4] = {0ull, 0ull, 0ull, 0ull};

    auto step = [&](float x) {
        hfull[15] = pk2(x, 0.0f);
        u64 acc[RPT];
        {   // jp = 0 initializes accumulators
#pragma unroll
            for (int rp = 0; rp < 4; rp++) {
                ulonglong2 w = wp[rp];
                acc[2 * rp]     = fmul2(w.x, hfull[0]);
                acc[2 * rp + 1] = fmul2(w.y, hfull[0]);
            }
        }
#pragma unroll
        for (int jp = 1; jp < NJP; jp++) {
            const u64 hj = hfull[jp];
#pragma unroll
            for (int rp = 0; rp < 4; rp++) {
                ulonglong2 w = wp[jp * 4 + rp];
                acc[2 * rp]     = ffma2(w.x, hj, acc[2 * rp]);
                acc[2 * rp + 1] = ffma2(w.y, hj, acc[2 * rp + 1]);
            }
        }
        // horizontal reduce + modReLU on own 8 rows (pad rows yield exactly 0)
        float hn[RPT];
#pragma unroll
        for (int r = 0; r < RPT; r++) {
            float lo, hi;
            upk2(lo, hi, acc[r]);
            const float z = lo + hi;
            const float m = fmaxf(fabsf(z) + bmr[r], 0.0f);
            hn[r] = copysignf(m, z);
        }
#pragma unroll
        for (int rp = 0; rp < 4; rp++) own[rp] = pk2(hn[2 * rp], hn[2 * rp + 1]);
        // broadcast the 15 live h'-pairs across the quad (pair p owned by sub p>>2)
#pragma unroll
        for (int p = 0; p < 15; p++) {
            const int src = (lane & ~3) | (p >> 2);
            hfull[p] = __shfl_sync(0xffffffffu, own[p & 3], src);
        }
    };

    float2 xv = __ldg(&xrow[0]);
    const int NIT = T_SEQ / 2;  // 392
    for (int t2 = 0; t2 < NIT; ++t2) {
        const unsigned nidx = min((unsigned)(t2 + 1), (unsigned)(NIT - 1));
        float2 xn = __ldg(&xrow[nidx]);
        step(xv.x);
        step(xv.y);
        xv = xn;
    }

    // Linear head: full h is register-resident in every thread; sub s does
    // classes {s, s+4, s+8} (covers 0..9 across the quad).
    float h[HID];
#pragma unroll
    for (int p = 0; p < 15; p++) upk2(h[2 * p], h[2 * p + 1], hfull[p]);

    for (int c = sub; c < NCLS; c += SUBS) {
        float a = __ldg(&b_lin[c]);
#pragma unroll
        for (int i = 0; i < HID; i++)
            a = fmaf(__ldg(&W_lin[c * HID + i]), h[i], a);
        out[(size_t)elem * NCLS + c] = a;
    }
}

extern "C" void kernel_launch(void* const* d_in, const int* in_sizes, int n_in,
                              void* d_out, int out_size) {
    const float* inputs = (const float*)d_in[0];
    const float* W_ih   = (const float*)d_in[1];
    const float* W_hh   = (const float*)d_in[2];
    const float* b_mod  = (const float*)d_in[3];
    const float* W_lin  = (const float*)d_in[4];
    const float* b_lin  = (const float*)d_in[5];
    float* out = (float*)d_out;

    // 4 threads per element: 16384*4 = 65536 threads = 512 CTAs x 128
    rnn_modrelu_kernel<<<B_TOT / 32, 128>>>(inputs, W_ih, W_hh, b_mod,
                                            W_lin, b_lin, out);
}

// round 13
// speedup vs baseline: 2.3921x; 2.3921x over previous
#include <cuda_runtime.h>
#include <cstdint>

#define B_TOT 16384
#define T_SEQ 784
#define HID   30
#define NCLS  10
#define NJP   16          // 15 h-pairs (cols 0..29) + 1 x-pair
#define RPT   8           // rows per thread (30 padded to 32, 4 subs x 8)
#define SUBS  4
#define WSTRIDE (NJP * RPT + 2)   // 130 u64 per sub: +16B pad => subs hit disjoint banks

typedef unsigned long long u64;

// ---- packed f32x2 helpers (Blackwell FFMA2 path, PTX-only) ----
__device__ __forceinline__ u64 pk2(float lo, float hi) {
    u64 r; asm("mov.b64 %0, {%1, %2};" : "=l"(r) : "f"(lo), "f"(hi)); return r;
}
__device__ __forceinline__ void upk2(float& lo, float& hi, u64 v) {
    asm("mov.b64 {%0, %1}, %2;" : "=f"(lo), "=f"(hi) : "l"(v));
}
__device__ __forceinline__ u64 ffma2(u64 a, u64 b, u64 c) {
    u64 d; asm("fma.rn.f32x2 %0, %1, %2, %3;" : "=l"(d) : "l"(a), "l"(b), "l"(c));
    return d;
}
__device__ __forceinline__ u64 fmul2(u64 a, u64 b) {
    u64 d; asm("mul.rn.f32x2 %0, %1, %2;" : "=l"(d) : "l"(a), "l"(b));
    return d;
}

// 4 threads cooperate on one batch element (sub = tid&3 owns rows 8*sub..8*sub+7,
// rows 30,31 are zero-padded). Each step: every thread contracts the full packed
// h vector against its 8 weight rows from SMEM, applies modReLU to its 8
// outputs, then the 15 packed h'-pairs are broadcast across the quad with
// shfl.idx. 2048 warps total.
// NOTE: no min-blocks clause -- R11 proved that forcing occupancy 4 caps regs
// at 128 and makes ptxas spill (L1 70%, DRAM 12%, 3048us). Let the RF set
// occupancy naturally (~150-190 regs -> 2-3 CTAs/SM).
__global__ void __launch_bounds__(128)
rnn_modrelu_kernel(const float* __restrict__ inputs,   // [B, 784]
                   const float* __restrict__ W_ih,     // [30, 1]
                   const float* __restrict__ W_hh,     // [30, 30]
                   const float* __restrict__ b_mod,    // [30]
                   const float* __restrict__ W_lin,    // [10, 30]
                   const float* __restrict__ b_lin,    // [10]
                   float* __restrict__ out)            // [B, 10]
{
    // wts[sub*WSTRIDE + jp*8 + k] = packed weights for row i=8*sub+k, col pair jp:
    //   jp<15 : (W_hh[i][2jp], W_hh[i][2jp+1])   (zero if i>=30)
    //   jp=15 : (W_ih[i], 0)
    __shared__ __align__(16) u64 wts[SUBS * WSTRIDE];

    const int tid = threadIdx.x;
    for (int idx = tid; idx < SUBS * NJP * RPT; idx += 128) {
        const int s  = idx / (NJP * RPT);
        const int rm = idx % (NJP * RPT);
        const int jp = rm / RPT;
        const int k  = rm % RPT;
        const int i  = s * RPT + k;
        float lo = 0.0f, hi = 0.0f;
        if (i < HID) {
            if (jp < 15) { lo = W_hh[i * HID + 2 * jp]; hi = W_hh[i * HID + 2 * jp + 1]; }
            else         { lo = W_ih[i]; }
        }
        wts[s * WSTRIDE + jp * RPT + k] = pk2(lo, hi);
    }
    __syncthreads();

    const int lane = tid & 31;
    const int sub  = tid & 3;
    const int elem = blockIdx.x * 32 + (tid >> 2);

    float bmr[RPT];
#pragma unroll
    for (int r = 0; r < RPT; r++) {
        const int i = sub * RPT + r;
        bmr[r] = (i < HID) ? __ldg(&b_mod[i]) : 0.0f;
    }

    const float2* __restrict__ xrow =
        reinterpret_cast<const float2*>(inputs + (size_t)elem * T_SEQ);
    const ulonglong2* __restrict__ wp =
        reinterpret_cast<const ulonglong2*>(wts + sub * WSTRIDE);

    u64 hfull[NJP];
#pragma unroll
    for (int p = 0; p < NJP; p++) hfull[p] = 0ull;
    u64 own[4] = {0ull, 0ull, 0ull, 0ull};

    auto step = [&](float x) {
        hfull[15] = pk2(x, 0.0f);
        u64 acc[RPT];
        {   // jp = 0 initializes accumulators
#pragma unroll
            for (int rp = 0; rp < 4; rp++) {
                ulonglong2 w = wp[rp];
                acc[2 * rp]     = fmul2(w.x, hfull[0]);
                acc[2 * rp + 1] = fmul2(w.y, hfull[0]);
            }
        }
#pragma unroll
        for (int jp = 1; jp < NJP; jp++) {
            const u64 hj = hfull[jp];
#pragma unroll
            for (int rp = 0; rp < 4; rp++) {
                ulonglong2 w = wp[jp * 4 + rp];
                acc[2 * rp]     = ffma2(w.x, hj, acc[2 * rp]);
                acc[2 * rp + 1] = ffma2(w.y, hj, acc[2 * rp + 1]);
            }
        }
        // horizontal reduce + modReLU on own 8 rows (pad rows yield exactly 0)
        float hn[RPT];
#pragma unroll
        for (int r = 0; r < RPT; r++) {
            float lo, hi;
            upk2(lo, hi, acc[r]);
            const float z = lo + hi;
            const float m = fmaxf(fabsf(z) + bmr[r], 0.0f);
            hn[r] = copysignf(m, z);
        }
#pragma unroll
        for (int rp = 0; rp < 4; rp++) own[rp] = pk2(hn[2 * rp], hn[2 * rp + 1]);
        // broadcast the 15 live h'-pairs across the quad (pair p owned by sub p>>2)
#pragma unroll
        for (int p = 0; p < 15; p++) {
            const int src = (lane & ~3) | (p >> 2);
            hfull[p] = __shfl_sync(0xffffffffu, own[p & 3], src);
        }
    };

    float2 xv = __ldg(&xrow[0]);
    const int NIT = T_SEQ / 2;  // 392
    for (int t2 = 0; t2 < NIT; ++t2) {
        const unsigned nidx = min((unsigned)(t2 + 1), (unsigned)(NIT - 1));
        float2 xn = __ldg(&xrow[nidx]);
        step(xv.x);
        step(xv.y);
        xv = xn;
    }

    // Linear head: full h is register-resident in every thread; sub s does
    // classes {s, s+4, s+8} (covers 0..9 across the quad).
    float h[HID];
#pragma unroll
    for (int p = 0; p < 15; p++) upk2(h[2 * p], h[2 * p + 1], hfull[p]);

    for (int c = sub; c < NCLS; c += SUBS) {
        float a = __ldg(&b_lin[c]);
#pragma unroll
        for (int i = 0; i < HID; i++)
            a = fmaf(__ldg(&W_lin[c * HID + i]), h[i], a);
        out[(size_t)elem * NCLS + c] = a;
    }
}

extern "C" void kernel_launch(void* const* d_in, const int* in_sizes, int n_in,
                              void* d_out, int out_size) {
    const float* inputs = (const float*)d_in[0];
    const float* W_ih   = (const float*)d_in[1];
    const float* W_hh   = (const float*)d_in[2];
    const float* b_mod  = (const float*)d_in[3];
    const float* W_lin  = (const float*)d_in[4];
    const float* b_lin  = (const float*)d_in[5];
    float* out = (float*)d_out;

    // 4 threads per element: 16384*4 = 65536 threads = 512 CTAs x 128
    rnn_modrelu_kernel<<<B_TOT / 32, 128>>>(inputs, W_ih, W_hh, b_mod,
                                            W_lin, b_lin, out);
}